// round 1
// baseline (speedup 1.0000x reference)
#include <cuda_runtime.h>
#include <math.h>

#define T_STEPS 256
#define B_SZ    64
#define H_SZ    1024
#define O_SZ    1024
#define BH      (B_SZ * H_SZ)        // 65536
#define M_TOT   (T_STEPS * B_SZ)     // 16384
#define KSPLIT  8

// Scratch (static device arrays are the sanctioned allocation-free scratch)
__device__ float g_acc[(size_t)M_TOT * H_SZ];   // ix + bi + bh (pre-activation, per step t)
__device__ float g_hs [(size_t)M_TOT * H_SZ];   // tanh hidden states, [t][b][h]
__device__ float g_parts[KSPLIT * BH];          // k-split partials of h @ Wh

// ---------------------------------------------------------------------------
// K1: g_acc[t*B+b][j] = sum_k emb[input[b][t]][k] * Wi[k][j] + bi[j] + bh[j]
// Tiles: 128(M) x 128(N), k-chunk 16, double-buffered smem, 8x8 per thread.
// ---------------------------------------------------------------------------
__global__ __launch_bounds__(256) void gemm_ix(
    const int* __restrict__ input, const float* __restrict__ emb,
    const float* __restrict__ Wi, const float* __restrict__ bi,
    const float* __restrict__ bh)
{
    __shared__ float As[2][16][128];
    __shared__ float Bs[2][16][128];
    __shared__ int   idxs[128];

    const int tid   = threadIdx.x;
    const int ntile = blockIdx.x;   // 0..7
    const int mtile = blockIdx.y;   // 0..127

    if (tid < 128) {
        int m  = mtile * 128 + tid;
        int tt = m >> 6, bb = m & 63;
        idxs[tid] = input[bb * T_STEPS + tt];
    }
    __syncthreads();

    const int ar  = tid >> 2;       // 0..63 (A rows; +64 for second half)
    const int ak4 = tid & 3;        // float4 slot in k-chunk
    const int bk  = tid >> 5;       // 0..7  (B k rows; +8 for second half)
    const int bc4 = tid & 31;       // float4 slot in n
    const float* WiBase = Wi + ntile * 128 + bc4 * 4;

    const size_t rowA0 = (size_t)idxs[ar] * H_SZ;
    const size_t rowA1 = (size_t)idxs[ar + 64] * H_SZ;

    float4 a0 = *(const float4*)(emb + rowA0 + ak4 * 4);
    float4 a1 = *(const float4*)(emb + rowA1 + ak4 * 4);
    float4 b0 = *(const float4*)(WiBase + (size_t)bk * H_SZ);
    float4 b1 = *(const float4*)(WiBase + (size_t)(bk + 8) * H_SZ);

    float acc[8][8];
#pragma unroll
    for (int i = 0; i < 8; i++)
#pragma unroll
        for (int j = 0; j < 8; j++) acc[i][j] = 0.f;

    const int ty = tid >> 4, tx = tid & 15;

    // store chunk 0
    As[0][ak4*4+0][ar] = a0.x; As[0][ak4*4+1][ar] = a0.y;
    As[0][ak4*4+2][ar] = a0.z; As[0][ak4*4+3][ar] = a0.w;
    As[0][ak4*4+0][ar+64] = a1.x; As[0][ak4*4+1][ar+64] = a1.y;
    As[0][ak4*4+2][ar+64] = a1.z; As[0][ak4*4+3][ar+64] = a1.w;
    *(float4*)&Bs[0][bk][bc4*4]   = b0;
    *(float4*)&Bs[0][bk+8][bc4*4] = b1;
    __syncthreads();

    for (int c = 0; c < 64; c++) {
        const int cur = c & 1;
        if (c < 63) {
            int k0 = (c + 1) * 16;
            a0 = *(const float4*)(emb + rowA0 + k0 + ak4 * 4);
            a1 = *(const float4*)(emb + rowA1 + k0 + ak4 * 4);
            b0 = *(const float4*)(WiBase + (size_t)(k0 + bk) * H_SZ);
            b1 = *(const float4*)(WiBase + (size_t)(k0 + bk + 8) * H_SZ);
        }
#pragma unroll
        for (int kk = 0; kk < 16; kk++) {
            float a[8], b[8];
            *(float4*)&a[0] = *(const float4*)&As[cur][kk][ty*8 + 0];
            *(float4*)&a[4] = *(const float4*)&As[cur][kk][ty*8 + 4];
            *(float4*)&b[0] = *(const float4*)&Bs[cur][kk][tx*8 + 0];
            *(float4*)&b[4] = *(const float4*)&Bs[cur][kk][tx*8 + 4];
#pragma unroll
            for (int i = 0; i < 8; i++)
#pragma unroll
                for (int j = 0; j < 8; j++)
                    acc[i][j] = fmaf(a[i], b[j], acc[i][j]);
        }
        if (c < 63) {
            const int nxt = cur ^ 1;
            As[nxt][ak4*4+0][ar] = a0.x; As[nxt][ak4*4+1][ar] = a0.y;
            As[nxt][ak4*4+2][ar] = a0.z; As[nxt][ak4*4+3][ar] = a0.w;
            As[nxt][ak4*4+0][ar+64] = a1.x; As[nxt][ak4*4+1][ar+64] = a1.y;
            As[nxt][ak4*4+2][ar+64] = a1.z; As[nxt][ak4*4+3][ar+64] = a1.w;
            *(float4*)&Bs[nxt][bk][bc4*4]   = b0;
            *(float4*)&Bs[nxt][bk+8][bc4*4] = b1;
        }
        __syncthreads();
    }

    float bsum[8];
#pragma unroll
    for (int j = 0; j < 8; j++) {
        int col = ntile * 128 + tx * 8 + j;
        bsum[j] = bi[col] + bh[col];
    }
#pragma unroll
    for (int i = 0; i < 8; i++) {
        int m = mtile * 128 + ty * 8 + i;
        float* dst = g_acc + (size_t)m * H_SZ + ntile * 128 + tx * 8;
        *(float4*)(dst + 0) = make_float4(acc[i][0]+bsum[0], acc[i][1]+bsum[1],
                                          acc[i][2]+bsum[2], acc[i][3]+bsum[3]);
        *(float4*)(dst + 4) = make_float4(acc[i][4]+bsum[4], acc[i][5]+bsum[5],
                                          acc[i][6]+bsum[6], acc[i][7]+bsum[7]);
    }
}

// ---------------------------------------------------------------------------
// K2a: per-step recurrence GEMM, k-split into 8 partials.
// grid (16 col-tiles, 8 k-chunks); each CTA: 64x64 over k=128; 4x4 per thread.
// ---------------------------------------------------------------------------
__global__ __launch_bounds__(256) void gemm_rec(
    int t, const float* __restrict__ hidden0, const float* __restrict__ Wh)
{
    const float* hp = (t == 0) ? hidden0 : (const float*)(g_hs + (size_t)(t - 1) * BH);
    __shared__ float As[2][16][64];
    __shared__ float Ws[2][16][64];

    const int tid = threadIdx.x;
    const int ct = blockIdx.x;      // 0..15 col tile
    const int kc = blockIdx.y;      // 0..7  k chunk

    const int ar  = tid >> 2;       // 0..63 row
    const int ak4 = tid & 3;
    const int wk  = tid >> 4;       // 0..15 k
    const int wc4 = tid & 15;

    const float* hBase = hp + (size_t)ar * H_SZ + kc * 128 + ak4 * 4;
    const float* wBase = Wh + (size_t)(kc * 128 + wk) * H_SZ + ct * 64 + wc4 * 4;

    float4 a0 = *(const float4*)(hBase);
    float4 w0 = *(const float4*)(wBase);

    float acc[4][4];
#pragma unroll
    for (int i = 0; i < 4; i++)
#pragma unroll
        for (int j = 0; j < 4; j++) acc[i][j] = 0.f;

    const int ty = tid >> 4, tx = tid & 15;

    As[0][ak4*4+0][ar] = a0.x; As[0][ak4*4+1][ar] = a0.y;
    As[0][ak4*4+2][ar] = a0.z; As[0][ak4*4+3][ar] = a0.w;
    *(float4*)&Ws[0][wk][wc4*4] = w0;
    __syncthreads();

    for (int c = 0; c < 8; c++) {
        const int cur = c & 1;
        if (c < 7) {
            a0 = *(const float4*)(hBase + (c + 1) * 16);
            w0 = *(const float4*)(wBase + (size_t)(c + 1) * 16 * H_SZ);
        }
#pragma unroll
        for (int kk = 0; kk < 16; kk++) {
            float a[4], b[4];
            *(float4*)&a[0] = *(const float4*)&As[cur][kk][ty*4];
            *(float4*)&b[0] = *(const float4*)&Ws[cur][kk][tx*4];
#pragma unroll
            for (int i = 0; i < 4; i++)
#pragma unroll
                for (int j = 0; j < 4; j++)
                    acc[i][j] = fmaf(a[i], b[j], acc[i][j]);
        }
        if (c < 7) {
            const int nxt = cur ^ 1;
            As[nxt][ak4*4+0][ar] = a0.x; As[nxt][ak4*4+1][ar] = a0.y;
            As[nxt][ak4*4+2][ar] = a0.z; As[nxt][ak4*4+3][ar] = a0.w;
            *(float4*)&Ws[nxt][wk][wc4*4] = w0;
        }
        __syncthreads();
    }

    float* p = g_parts + kc * BH;
#pragma unroll
    for (int i = 0; i < 4; i++) {
        *(float4*)(p + (size_t)(ty*4 + i) * H_SZ + ct * 64 + tx * 4) =
            make_float4(acc[i][0], acc[i][1], acc[i][2], acc[i][3]);
    }
}

// ---------------------------------------------------------------------------
// K2b: deterministic reduce of 8 partials + pre-activation, then tanh -> hs[t]
// ---------------------------------------------------------------------------
__global__ __launch_bounds__(256) void reduce_tanh(int t)
{
    int i = blockIdx.x * blockDim.x + threadIdx.x;     // float4 index, 0..16383
    float4 a = ((const float4*)(g_acc + (size_t)t * BH))[i];
#pragma unroll
    for (int kc = 0; kc < KSPLIT; kc++) {
        float4 p = ((const float4*)(g_parts + kc * BH))[i];
        a.x += p.x; a.y += p.y; a.z += p.z; a.w += p.w;
    }
    a.x = tanhf(a.x); a.y = tanhf(a.y); a.z = tanhf(a.z); a.w = tanhf(a.w);
    ((float4*)(g_hs + (size_t)t * BH))[i] = a;
}

// ---------------------------------------------------------------------------
// K3: out[b][t][o] = sum_h hs[t][b][h] * Wo[h][o] + bo[o]
// Same 128x128 structure as K1, no gather; writes with [b][t] remap.
// ---------------------------------------------------------------------------
__global__ __launch_bounds__(256) void gemm_out(
    const float* __restrict__ Wo, const float* __restrict__ bo,
    float* __restrict__ out)
{
    __shared__ float As[2][16][128];
    __shared__ float Bs[2][16][128];

    const int tid   = threadIdx.x;
    const int ntile = blockIdx.x;
    const int mtile = blockIdx.y;

    const int ar  = tid >> 2;
    const int ak4 = tid & 3;
    const int bk  = tid >> 5;
    const int bc4 = tid & 31;
    const float* WoBase = Wo + ntile * 128 + bc4 * 4;

    const float* rowA0 = g_hs + (size_t)(mtile * 128 + ar) * H_SZ;
    const float* rowA1 = g_hs + (size_t)(mtile * 128 + ar + 64) * H_SZ;

    float4 a0 = *(const float4*)(rowA0 + ak4 * 4);
    float4 a1 = *(const float4*)(rowA1 + ak4 * 4);
    float4 b0 = *(const float4*)(WoBase + (size_t)bk * O_SZ);
    float4 b1 = *(const float4*)(WoBase + (size_t)(bk + 8) * O_SZ);

    float acc[8][8];
#pragma unroll
    for (int i = 0; i < 8; i++)
#pragma unroll
        for (int j = 0; j < 8; j++) acc[i][j] = 0.f;

    const int ty = tid >> 4, tx = tid & 15;

    As[0][ak4*4+0][ar] = a0.x; As[0][ak4*4+1][ar] = a0.y;
    As[0][ak4*4+2][ar] = a0.z; As[0][ak4*4+3][ar] = a0.w;
    As[0][ak4*4+0][ar+64] = a1.x; As[0][ak4*4+1][ar+64] = a1.y;
    As[0][ak4*4+2][ar+64] = a1.z; As[0][ak4*4+3][ar+64] = a1.w;
    *(float4*)&Bs[0][bk][bc4*4]   = b0;
    *(float4*)&Bs[0][bk+8][bc4*4] = b1;
    __syncthreads();

    for (int c = 0; c < 64; c++) {
        const int cur = c & 1;
        if (c < 63) {
            int k0 = (c + 1) * 16;
            a0 = *(const float4*)(rowA0 + k0 + ak4 * 4);
            a1 = *(const float4*)(rowA1 + k0 + ak4 * 4);
            b0 = *(const float4*)(WoBase + (size_t)(k0 + bk) * O_SZ);
            b1 = *(const float4*)(WoBase + (size_t)(k0 + bk + 8) * O_SZ);
        }
#pragma unroll
        for (int kk = 0; kk < 16; kk++) {
            float a[8], b[8];
            *(float4*)&a[0] = *(const float4*)&As[cur][kk][ty*8 + 0];
            *(float4*)&a[4] = *(const float4*)&As[cur][kk][ty*8 + 4];
            *(float4*)&b[0] = *(const float4*)&Bs[cur][kk][tx*8 + 0];
            *(float4*)&b[4] = *(const float4*)&Bs[cur][kk][tx*8 + 4];
#pragma unroll
            for (int i = 0; i < 8; i++)
#pragma unroll
                for (int j = 0; j < 8; j++)
                    acc[i][j] = fmaf(a[i], b[j], acc[i][j]);
        }
        if (c < 63) {
            const int nxt = cur ^ 1;
            As[nxt][ak4*4+0][ar] = a0.x; As[nxt][ak4*4+1][ar] = a0.y;
            As[nxt][ak4*4+2][ar] = a0.z; As[nxt][ak4*4+3][ar] = a0.w;
            As[nxt][ak4*4+0][ar+64] = a1.x; As[nxt][ak4*4+1][ar+64] = a1.y;
            As[nxt][ak4*4+2][ar+64] = a1.z; As[nxt][ak4*4+3][ar+64] = a1.w;
            *(float4*)&Bs[nxt][bk][bc4*4]   = b0;
            *(float4*)&Bs[nxt][bk+8][bc4*4] = b1;
        }
        __syncthreads();
    }

    float bsum[8];
#pragma unroll
    for (int j = 0; j < 8; j++) bsum[j] = bo[ntile * 128 + tx * 8 + j];

#pragma unroll
    for (int i = 0; i < 8; i++) {
        int m  = mtile * 128 + ty * 8 + i;
        int bb = m & 63, tt = m >> 6;
        float* dst = out + ((size_t)bb * T_STEPS + tt) * O_SZ + ntile * 128 + tx * 8;
        *(float4*)(dst + 0) = make_float4(acc[i][0]+bsum[0], acc[i][1]+bsum[1],
                                          acc[i][2]+bsum[2], acc[i][3]+bsum[3]);
        *(float4*)(dst + 4) = make_float4(acc[i][4]+bsum[4], acc[i][5]+bsum[5],
                                          acc[i][6]+bsum[6], acc[i][7]+bsum[7]);
    }
}

__global__ void copy_hidden(float* __restrict__ dst)
{
    int i = blockIdx.x * blockDim.x + threadIdx.x;
    dst[i] = g_hs[(size_t)(T_STEPS - 1) * BH + i];
}

// ---------------------------------------------------------------------------
extern "C" void kernel_launch(void* const* d_in, const int* in_sizes, int n_in,
                              void* d_out, int out_size)
{
    const int*   input   = (const int*)  d_in[0];
    const float* hidden0 = (const float*)d_in[1];
    const float* emb     = (const float*)d_in[2];
    const float* Wi      = (const float*)d_in[3];
    const float* bi      = (const float*)d_in[4];
    const float* Wh      = (const float*)d_in[5];
    const float* bh      = (const float*)d_in[6];
    const float* Wo      = (const float*)d_in[7];
    const float* bo      = (const float*)d_in[8];
    float* out = (float*)d_out;

    gemm_ix<<<dim3(8, 128), 256>>>(input, emb, Wi, bi, bh);

    for (int t = 0; t < T_STEPS; t++) {
        gemm_rec<<<dim3(16, KSPLIT), 256>>>(t, hidden0, Wh);
        reduce_tanh<<<64, 256>>>(t);
    }

    gemm_out<<<dim3(8, 128), 256>>>(Wo, bo, out);

    if (out_size >= M_TOT * O_SZ + BH) {
        copy_hidden<<<256, 256>>>(out + (size_t)M_TOT * O_SZ);
    }
}

// round 2
// speedup vs baseline: 1.0334x; 1.0334x over previous
#include <cuda_runtime.h>
#include <math.h>

#define T_STEPS 256
#define B_SZ    64
#define H_SZ    1024
#define O_SZ    1024
#define BH      (B_SZ * H_SZ)        // 65536
#define M_TOT   (T_STEPS * B_SZ)     // 16384
#define KSPLIT  8
#define NCTA    128

typedef unsigned long long u64;

// ---- packed fp32x2 helpers (sm_103a FFMA2) --------------------------------
__device__ __forceinline__ u64 pk2(float x) {
    u64 r; asm("mov.b64 %0, {%1, %1};" : "=l"(r) : "f"(x)); return r;
}
__device__ __forceinline__ u64 fma2(u64 a, u64 b, u64 c) {
    u64 d; asm("fma.rn.f32x2 %0, %1, %2, %3;" : "=l"(d) : "l"(a), "l"(b), "l"(c));
    return d;
}
__device__ __forceinline__ float2 upk(u64 v) {
    float2 r; asm("mov.b64 {%0, %1}, %2;" : "=f"(r.x), "=f"(r.y) : "l"(v)); return r;
}

// ---- scratch ---------------------------------------------------------------
__device__ float g_acc[(size_t)M_TOT * H_SZ];   // ix + bi + bh per (t,b,h)
__device__ float g_hs [(size_t)M_TOT * H_SZ];   // hidden states [t][b][h]
__device__ float g_parts[KSPLIT * BH];          // k-split partials of h @ Wh
__device__ unsigned g_cnt[2];                   // barrier arrival counters
__device__ unsigned g_flag[2];                  // barrier release flags (monotonic)

// ---------------------------------------------------------------------------
// K1: g_acc[t*B+b][j] = emb[input[b][t]] @ Wi + bi + bh   (f32x2 inner)
// 128x128 tile, k-chunk 16, double-buffered, 8x8 per thread as 8x4 f32x2.
// ---------------------------------------------------------------------------
__global__ __launch_bounds__(256) void gemm_ix(
    const int* __restrict__ input, const float* __restrict__ emb,
    const float* __restrict__ Wi, const float* __restrict__ bi,
    const float* __restrict__ bh)
{
    __shared__ __align__(16) float As[2][16][128];
    __shared__ __align__(16) float Bs[2][16][128];
    __shared__ int idxs[128];

    const int tid   = threadIdx.x;
    const int ntile = blockIdx.x;   // 0..7
    const int mtile = blockIdx.y;   // 0..127

    if (tid < 128) {
        int m  = mtile * 128 + tid;
        int tt = m >> 6, bb = m & 63;
        idxs[tid] = input[bb * T_STEPS + tt];
    }
    __syncthreads();

    const int ar  = tid >> 2;
    const int ak4 = tid & 3;
    const int bk  = tid >> 5;
    const int bc4 = tid & 31;
    const float* WiBase = Wi + ntile * 128 + bc4 * 4;

    const size_t rowA0 = (size_t)idxs[ar] * H_SZ;
    const size_t rowA1 = (size_t)idxs[ar + 64] * H_SZ;

    float4 a0 = *(const float4*)(emb + rowA0 + ak4 * 4);
    float4 a1 = *(const float4*)(emb + rowA1 + ak4 * 4);
    float4 b0 = *(const float4*)(WiBase + (size_t)bk * H_SZ);
    float4 b1 = *(const float4*)(WiBase + (size_t)(bk + 8) * H_SZ);

    u64 acc2[8][4];
#pragma unroll
    for (int i = 0; i < 8; i++)
#pragma unroll
        for (int j = 0; j < 4; j++) acc2[i][j] = 0ull;

    const int ty = tid >> 4, tx = tid & 15;

    As[0][ak4*4+0][ar] = a0.x; As[0][ak4*4+1][ar] = a0.y;
    As[0][ak4*4+2][ar] = a0.z; As[0][ak4*4+3][ar] = a0.w;
    As[0][ak4*4+0][ar+64] = a1.x; As[0][ak4*4+1][ar+64] = a1.y;
    As[0][ak4*4+2][ar+64] = a1.z; As[0][ak4*4+3][ar+64] = a1.w;
    *(float4*)&Bs[0][bk][bc4*4]   = b0;
    *(float4*)&Bs[0][bk+8][bc4*4] = b1;
    __syncthreads();

    for (int c = 0; c < 64; c++) {
        const int cur = c & 1;
        if (c < 63) {
            int k0 = (c + 1) * 16;
            a0 = *(const float4*)(emb + rowA0 + k0 + ak4 * 4);
            a1 = *(const float4*)(emb + rowA1 + k0 + ak4 * 4);
            b0 = *(const float4*)(WiBase + (size_t)(k0 + bk) * H_SZ);
            b1 = *(const float4*)(WiBase + (size_t)(k0 + bk + 8) * H_SZ);
        }
#pragma unroll
        for (int kk = 0; kk < 16; kk++) {
            float a[8];
            *(float4*)&a[0] = *(const float4*)&As[cur][kk][ty*8 + 0];
            *(float4*)&a[4] = *(const float4*)&As[cur][kk][ty*8 + 4];
            ulonglong2 bb0 = *(const ulonglong2*)&Bs[cur][kk][tx*8 + 0];
            ulonglong2 bb1 = *(const ulonglong2*)&Bs[cur][kk][tx*8 + 4];
#pragma unroll
            for (int i = 0; i < 8; i++) {
                u64 a2 = pk2(a[i]);
                acc2[i][0] = fma2(a2, bb0.x, acc2[i][0]);
                acc2[i][1] = fma2(a2, bb0.y, acc2[i][1]);
                acc2[i][2] = fma2(a2, bb1.x, acc2[i][2]);
                acc2[i][3] = fma2(a2, bb1.y, acc2[i][3]);
            }
        }
        if (c < 63) {
            const int nxt = cur ^ 1;
            As[nxt][ak4*4+0][ar] = a0.x; As[nxt][ak4*4+1][ar] = a0.y;
            As[nxt][ak4*4+2][ar] = a0.z; As[nxt][ak4*4+3][ar] = a0.w;
            As[nxt][ak4*4+0][ar+64] = a1.x; As[nxt][ak4*4+1][ar+64] = a1.y;
            As[nxt][ak4*4+2][ar+64] = a1.z; As[nxt][ak4*4+3][ar+64] = a1.w;
            *(float4*)&Bs[nxt][bk][bc4*4]   = b0;
            *(float4*)&Bs[nxt][bk+8][bc4*4] = b1;
        }
        __syncthreads();
    }

    float bsum[8];
#pragma unroll
    for (int j = 0; j < 8; j++) {
        int col = ntile * 128 + tx * 8 + j;
        bsum[j] = bi[col] + bh[col];
    }
#pragma unroll
    for (int i = 0; i < 8; i++) {
        int m = mtile * 128 + ty * 8 + i;
        float* dst = g_acc + (size_t)m * H_SZ + ntile * 128 + tx * 8;
        float2 q0 = upk(acc2[i][0]), q1 = upk(acc2[i][1]);
        float2 q2 = upk(acc2[i][2]), q3 = upk(acc2[i][3]);
        *(float4*)(dst + 0) = make_float4(q0.x+bsum[0], q0.y+bsum[1],
                                          q1.x+bsum[2], q1.y+bsum[3]);
        *(float4*)(dst + 4) = make_float4(q2.x+bsum[4], q2.y+bsum[5],
                                          q3.x+bsum[6], q3.y+bsum[7]);
    }
}

// ---------------------------------------------------------------------------
// Grid barrier: sense-free monotonic-flag barrier, replay-safe (no reset of
// the flag; counter self-resets via last arriver). All 128 CTAs co-resident.
// ---------------------------------------------------------------------------
__device__ __forceinline__ void grid_barrier(int slot) {
    __syncthreads();
    if (threadIdx.x == 0) {
        volatile unsigned* fl = &g_flag[slot];
        unsigned prev = *fl;                 // read BEFORE arriving
        __threadfence();                     // publish this CTA's writes (cumulative via bar)
        unsigned old = atomicAdd(&g_cnt[slot], 1u);
        if (old == NCTA - 1) {
            atomicExch(&g_cnt[slot], 0u);
            __threadfence();
            atomicAdd(&g_flag[slot], 1u);    // release
        } else {
            while (*fl == prev) { }          // spin (volatile -> strong load)
        }
        __threadfence();                     // acquire
    }
    __syncthreads();
}

// ---------------------------------------------------------------------------
// K2: persistent recurrence. 128 CTAs: ct = blk&15 (64 cols), kc = blk>>4
// (128 k). Wh tile resident in smem (32 KB). Per step: h-tile streamed in
// 4 passes (reg-prefetched), f32x2 mainloop, partial -> gmem, barrier,
// fused 8-way reduce + tanh, barrier.
// ---------------------------------------------------------------------------
__global__ __launch_bounds__(256) void rec_persistent(
    const float* __restrict__ hidden0, const float* __restrict__ Wh,
    float* __restrict__ hid_out)
{
    __shared__ __align__(16) float Ws[128][64];  // Wh[kc*128 + k][ct*64 + n]
    __shared__ __align__(16) float As[32][68];   // h[b][k-window], k-major

    const int tid = threadIdx.x;
    const int ct  = blockIdx.x & 15;
    const int kc  = blockIdx.x >> 4;

    // one-time Wh tile load (coalesced, 128B per row-half)
    {
        int r = tid >> 1, half = tid & 1;
        const float* wsrc = Wh + (size_t)(kc * 128 + r) * H_SZ + ct * 64 + half * 32;
#pragma unroll
        for (int i = 0; i < 8; i++)
            *(float4*)&Ws[r][half * 32 + i * 4] = *(const float4*)(wsrc + i * 4);
    }

    const int ty = tid >> 4, tx = tid & 15;   // compute mapping: 16x16
    const int rr = tid >> 2, kq = tid & 3;    // As-fill mapping: 64 rows x 4

#pragma unroll 1
    for (int t = 0; t < T_STEPS; t++) {
        const float* src  = t ? (g_hs + (size_t)(t - 1) * BH) : hidden0;
        const float* srow = src + (size_t)rr * H_SZ + kc * 128;

        u64 acc[4][2];
#pragma unroll
        for (int i = 0; i < 4; i++) { acc[i][0] = 0ull; acc[i][1] = 0ull; }

        float4 pf0 = __ldcg((const float4*)(srow + kq * 4));
        float4 pf1 = __ldcg((const float4*)(srow + kq * 4 + 16));

#pragma unroll
        for (int pass = 0; pass < 4; pass++) {
            __syncthreads();                       // As free
            {
                int k4a = kq * 4, k4b = (kq + 4) * 4;
                As[k4a+0][rr] = pf0.x; As[k4a+1][rr] = pf0.y;
                As[k4a+2][rr] = pf0.z; As[k4a+3][rr] = pf0.w;
                As[k4b+0][rr] = pf1.x; As[k4b+1][rr] = pf1.y;
                As[k4b+2][rr] = pf1.z; As[k4b+3][rr] = pf1.w;
            }
            if (pass < 3) {
                pf0 = __ldcg((const float4*)(srow + (pass + 1) * 32 + kq * 4));
                pf1 = __ldcg((const float4*)(srow + (pass + 1) * 32 + kq * 4 + 16));
            }
            __syncthreads();                       // As ready
#pragma unroll
            for (int kk = 0; kk < 32; kk++) {
                float4 a4 = *(const float4*)&As[kk][ty * 4];
                ulonglong2 w2 = *(const ulonglong2*)&Ws[pass * 32 + kk][tx * 4];
                u64 a2;
                a2 = pk2(a4.x); acc[0][0]=fma2(a2,w2.x,acc[0][0]); acc[0][1]=fma2(a2,w2.y,acc[0][1]);
                a2 = pk2(a4.y); acc[1][0]=fma2(a2,w2.x,acc[1][0]); acc[1][1]=fma2(a2,w2.y,acc[1][1]);
                a2 = pk2(a4.z); acc[2][0]=fma2(a2,w2.x,acc[2][0]); acc[2][1]=fma2(a2,w2.y,acc[2][1]);
                a2 = pk2(a4.w); acc[3][0]=fma2(a2,w2.x,acc[3][0]); acc[3][1]=fma2(a2,w2.y,acc[3][1]);
            }
        }

        // partial store: rows ty*4+i, cols ct*64 + tx*4
        {
            float* p = g_parts + (size_t)kc * BH + (size_t)(ty * 4) * H_SZ + ct * 64 + tx * 4;
#pragma unroll
            for (int i = 0; i < 4; i++) {
                float2 lo = upk(acc[i][0]), hi = upk(acc[i][1]);
                *(float4*)(p + (size_t)i * H_SZ) = make_float4(lo.x, lo.y, hi.x, hi.y);
            }
        }

        grid_barrier(0);

        // fused reduce + tanh: CTA c handles floats [c*512, c*512+512)
        if (tid < 128) {
            size_t e = (size_t)blockIdx.x * 512 + (size_t)tid * 4;
            float4 a = *(const float4*)(g_acc + (size_t)t * BH + e);
#pragma unroll
            for (int k2 = 0; k2 < KSPLIT; k2++) {
                float4 q = __ldcg((const float4*)(g_parts + (size_t)k2 * BH + e));
                a.x += q.x; a.y += q.y; a.z += q.z; a.w += q.w;
            }
            a.x = tanhf(a.x); a.y = tanhf(a.y); a.z = tanhf(a.z); a.w = tanhf(a.w);
            *(float4*)(g_hs + (size_t)t * BH + e) = a;
            if (hid_out && t == T_STEPS - 1) *(float4*)(hid_out + e) = a;
        }

        grid_barrier(1);
    }
}

// ---------------------------------------------------------------------------
// K3: out[b][t][o] = hs[t][b] @ Wo + bo   (f32x2 inner, [b][t] remap on store)
// ---------------------------------------------------------------------------
__global__ __launch_bounds__(256) void gemm_out(
    const float* __restrict__ Wo, const float* __restrict__ bo,
    float* __restrict__ out)
{
    __shared__ __align__(16) float As[2][16][128];
    __shared__ __align__(16) float Bs[2][16][128];

    const int tid   = threadIdx.x;
    const int ntile = blockIdx.x;
    const int mtile = blockIdx.y;

    const int ar  = tid >> 2;
    const int ak4 = tid & 3;
    const int bk  = tid >> 5;
    const int bc4 = tid & 31;
    const float* WoBase = Wo + ntile * 128 + bc4 * 4;

    const float* rowA0 = g_hs + (size_t)(mtile * 128 + ar) * H_SZ;
    const float* rowA1 = g_hs + (size_t)(mtile * 128 + ar + 64) * H_SZ;

    float4 a0 = *(const float4*)(rowA0 + ak4 * 4);
    float4 a1 = *(const float4*)(rowA1 + ak4 * 4);
    float4 b0 = *(const float4*)(WoBase + (size_t)bk * O_SZ);
    float4 b1 = *(const float4*)(WoBase + (size_t)(bk + 8) * O_SZ);

    u64 acc2[8][4];
#pragma unroll
    for (int i = 0; i < 8; i++)
#pragma unroll
        for (int j = 0; j < 4; j++) acc2[i][j] = 0ull;

    const int ty = tid >> 4, tx = tid & 15;

    As[0][ak4*4+0][ar] = a0.x; As[0][ak4*4+1][ar] = a0.y;
    As[0][ak4*4+2][ar] = a0.z; As[0][ak4*4+3][ar] = a0.w;
    As[0][ak4*4+0][ar+64] = a1.x; As[0][ak4*4+1][ar+64] = a1.y;
    As[0][ak4*4+2][ar+64] = a1.z; As[0][ak4*4+3][ar+64] = a1.w;
    *(float4*)&Bs[0][bk][bc4*4]   = b0;
    *(float4*)&Bs[0][bk+8][bc4*4] = b1;
    __syncthreads();

    for (int c = 0; c < 64; c++) {
        const int cur = c & 1;
        if (c < 63) {
            int k0 = (c + 1) * 16;
            a0 = *(const float4*)(rowA0 + k0 + ak4 * 4);
            a1 = *(const float4*)(rowA1 + k0 + ak4 * 4);
            b0 = *(const float4*)(WoBase + (size_t)(k0 + bk) * O_SZ);
            b1 = *(const float4*)(WoBase + (size_t)(k0 + bk + 8) * O_SZ);
        }
#pragma unroll
        for (int kk = 0; kk < 16; kk++) {
            float a[8];
            *(float4*)&a[0] = *(const float4*)&As[cur][kk][ty*8 + 0];
            *(float4*)&a[4] = *(const float4*)&As[cur][kk][ty*8 + 4];
            ulonglong2 bb0 = *(const ulonglong2*)&Bs[cur][kk][tx*8 + 0];
            ulonglong2 bb1 = *(const ulonglong2*)&Bs[cur][kk][tx*8 + 4];
#pragma unroll
            for (int i = 0; i < 8; i++) {
                u64 a2 = pk2(a[i]);
                acc2[i][0] = fma2(a2, bb0.x, acc2[i][0]);
                acc2[i][1] = fma2(a2, bb0.y, acc2[i][1]);
                acc2[i][2] = fma2(a2, bb1.x, acc2[i][2]);
                acc2[i][3] = fma2(a2, bb1.y, acc2[i][3]);
            }
        }
        if (c < 63) {
            const int nxt = cur ^ 1;
            As[nxt][ak4*4+0][ar] = a0.x; As[nxt][ak4*4+1][ar] = a0.y;
            As[nxt][ak4*4+2][ar] = a0.z; As[nxt][ak4*4+3][ar] = a0.w;
            As[nxt][ak4*4+0][ar+64] = a1.x; As[nxt][ak4*4+1][ar+64] = a1.y;
            As[nxt][ak4*4+2][ar+64] = a1.z; As[nxt][ak4*4+3][ar+64] = a1.w;
            *(float4*)&Bs[nxt][bk][bc4*4]   = b0;
            *(float4*)&Bs[nxt][bk+8][bc4*4] = b1;
        }
        __syncthreads();
    }

    float bsum[8];
#pragma unroll
    for (int j = 0; j < 8; j++) bsum[j] = bo[ntile * 128 + tx * 8 + j];

#pragma unroll
    for (int i = 0; i < 8; i++) {
        int m  = mtile * 128 + ty * 8 + i;
        int bb = m & 63, tt = m >> 6;
        float* dst = out + ((size_t)bb * T_STEPS + tt) * O_SZ + ntile * 128 + tx * 8;
        float2 q0 = upk(acc2[i][0]), q1 = upk(acc2[i][1]);
        float2 q2 = upk(acc2[i][2]), q3 = upk(acc2[i][3]);
        *(float4*)(dst + 0) = make_float4(q0.x+bsum[0], q0.y+bsum[1],
                                          q1.x+bsum[2], q1.y+bsum[3]);
        *(float4*)(dst + 4) = make_float4(q2.x+bsum[4], q2.y+bsum[5],
                                          q3.x+bsum[6], q3.y+bsum[7]);
    }
}

// ---------------------------------------------------------------------------
extern "C" void kernel_launch(void* const* d_in, const int* in_sizes, int n_in,
                              void* d_out, int out_size)
{
    const int*   input   = (const int*)  d_in[0];
    const float* hidden0 = (const float*)d_in[1];
    const float* emb     = (const float*)d_in[2];
    const float* Wi      = (const float*)d_in[3];
    const float* bi      = (const float*)d_in[4];
    const float* Wh      = (const float*)d_in[5];
    const float* bh      = (const float*)d_in[6];
    const float* Wo      = (const float*)d_in[7];
    const float* bo      = (const float*)d_in[8];
    float* out = (float*)d_out;

    float* hid_out = (out_size >= M_TOT * O_SZ + BH) ? out + (size_t)M_TOT * O_SZ
                                                     : (float*)0;

    gemm_ix<<<dim3(8, 128), 256>>>(input, emb, Wi, bi, bh);
    rec_persistent<<<NCTA, 256>>>(hidden0, Wh, hid_out);
    gemm_out<<<dim3(8, 128), 256>>>(Wo, bo, out);
}

// round 4
// speedup vs baseline: 1.2955x; 1.2536x over previous
#include <cuda_runtime.h>
#include <cuda_bf16.h>
#include <math.h>

#define T_STEPS 256
#define B_SZ    64
#define H_SZ    1024
#define O_SZ    1024
#define BH      (B_SZ * H_SZ)        // 65536
#define M_TOT   (T_STEPS * B_SZ)     // 16384
#define KC_REC  32                   // recurrence k-split
#define NCTA    128
#define PAD     40                   // smem row stride (bf16) for mma tiles

typedef unsigned long long u64;
typedef unsigned int u32;

// ---- packed fp32x2 helpers -------------------------------------------------
__device__ __forceinline__ u64 pk2(float x) {
    u64 r; asm("mov.b64 %0, {%1, %1};" : "=l"(r) : "f"(x)); return r;
}
__device__ __forceinline__ u64 fma2(u64 a, u64 b, u64 c) {
    u64 d; asm("fma.rn.f32x2 %0, %1, %2, %3;" : "=l"(d) : "l"(a), "l"(b), "l"(c));
    return d;
}
__device__ __forceinline__ float2 upk(u64 v) {
    float2 r; asm("mov.b64 {%0, %1}, %2;" : "=f"(r.x), "=f"(r.y) : "l"(v)); return r;
}

__device__ __forceinline__ u32 smem_u32(const void* p) {
    u32 a; asm("{ .reg .u64 t; cvta.to.shared.u64 t, %1; cvt.u32.u64 %0, t; }"
               : "=r"(a) : "l"(p));
    return a;
}

// ---- mma.sync helpers (plain PTX, no arch-'a' features) --------------------
__device__ __forceinline__ void ldmx4(u32& r0, u32& r1, u32& r2, u32& r3, u32 a) {
    asm volatile("ldmatrix.sync.aligned.m8n8.x4.shared.b16 {%0,%1,%2,%3}, [%4];"
                 : "=r"(r0), "=r"(r1), "=r"(r2), "=r"(r3) : "r"(a));
}
__device__ __forceinline__ void mma16816(float* c, const u32* a, const u32* b) {
    asm volatile(
        "mma.sync.aligned.m16n8k16.row.col.f32.bf16.bf16.f32 "
        "{%0,%1,%2,%3}, {%4,%5,%6,%7}, {%8,%9}, {%0,%1,%2,%3};"
        : "+f"(c[0]), "+f"(c[1]), "+f"(c[2]), "+f"(c[3])
        : "r"(a[0]), "r"(a[1]), "r"(a[2]), "r"(a[3]), "r"(b[0]), "r"(b[1]));
}

// ---- scratch ---------------------------------------------------------------
__device__ float g_acc[(size_t)M_TOT * H_SZ];      // ix + bi + bh
__device__ float g_hs [(size_t)M_TOT * H_SZ];      // fp32 hidden states
__device__ __nv_bfloat16 g_A1hi[(size_t)M_TOT * H_SZ];
__device__ __nv_bfloat16 g_A1lo[(size_t)M_TOT * H_SZ];
__device__ __nv_bfloat16 g_hsbhi[(size_t)M_TOT * H_SZ];
__device__ __nv_bfloat16 g_hsblo[(size_t)M_TOT * H_SZ];
__device__ __nv_bfloat16 g_WiThi[(size_t)H_SZ * H_SZ];   // [n][k]
__device__ __nv_bfloat16 g_WiTlo[(size_t)H_SZ * H_SZ];
__device__ __nv_bfloat16 g_WoThi[(size_t)H_SZ * O_SZ];
__device__ __nv_bfloat16 g_WoTlo[(size_t)H_SZ * O_SZ];
__device__ float g_parts[(size_t)KC_REC * BH];
__device__ float g_bias1[H_SZ];
__device__ unsigned g_cnt[2];
__device__ unsigned g_flag[2];

// ---------------------------------------------------------------------------
// Prep kernels
// ---------------------------------------------------------------------------
__global__ void prep_bias(const float* __restrict__ bi, const float* __restrict__ bh) {
    int i = blockIdx.x * 256 + threadIdx.x;
    g_bias1[i] = bi[i] + bh[i];
}

template<int W>
__global__ void prep_transpose(const float* __restrict__ src) {
    __shared__ float ts[32][33];
    __nv_bfloat16* dhi = W ? g_WoThi : g_WiThi;
    __nv_bfloat16* dlo = W ? g_WoTlo : g_WiTlo;
    int n0 = blockIdx.x * 32, k0 = blockIdx.y * 32;
    int tx = threadIdx.x & 31, ty = threadIdx.x >> 5;
#pragma unroll
    for (int i = 0; i < 4; i++)
        ts[ty + i * 8][tx] = src[(size_t)(k0 + ty + i * 8) * H_SZ + n0 + tx];
    __syncthreads();
#pragma unroll
    for (int i = 0; i < 4; i++) {
        int n = n0 + ty + i * 8;
        float v = ts[tx][ty + i * 8];
        __nv_bfloat16 h = __float2bfloat16(v);
        float r = v - __bfloat162float(h);
        dhi[(size_t)n * H_SZ + k0 + tx] = h;
        dlo[(size_t)n * H_SZ + k0 + tx] = __float2bfloat16(r);
    }
}

struct __align__(16) bf8 { __nv_bfloat16 v[8]; };

__global__ void prep_gather(const int* __restrict__ input, const float* __restrict__ emb) {
    size_t g = (size_t)blockIdx.x * 256 + threadIdx.x;
    size_t e = g * 8;
    int m = (int)(e >> 10), k = (int)(e & 1023);
    int t = m >> 6, b = m & 63;
    int row = input[b * T_STEPS + t];
    float4 v0 = *(const float4*)(emb + (size_t)row * H_SZ + k);
    float4 v1 = *(const float4*)(emb + (size_t)row * H_SZ + k + 4);
    float vv[8] = {v0.x, v0.y, v0.z, v0.w, v1.x, v1.y, v1.z, v1.w};
    bf8 hh, ll;
#pragma unroll
    for (int i = 0; i < 8; i++) {
        __nv_bfloat16 h = __float2bfloat16(vv[i]);
        hh.v[i] = h;
        ll.v[i] = __float2bfloat16(vv[i] - __bfloat162float(h));
    }
    *(bf8*)(g_A1hi + e) = hh;
    *(bf8*)(g_A1lo + e) = ll;
}

// ---------------------------------------------------------------------------
// mma.sync GEMM: C[m][n] = sum_k A[m][k]*B[n][k] + bias, bf16 3-term split.
// MODE 0: A=g_A1hi/lo, B=WiT, dst=g_acc, bias=g_bias1
// MODE 1: A=g_hsbhi/lo, B=WoT, dst=out with [b][t] remap, bias=bo
// CTA tile 128x128, 8 warps (4x2), warp tile m32 x n64, kc=32 double-buffered.
// ---------------------------------------------------------------------------
#define TILE_BF (128 * PAD)                 // bf16 elems per tile
#define SMEM_GEMM_BYTES (2 * 4 * TILE_BF * 2)   // 2 bufs * 4 tiles * bytes

template<int MODE>
__global__ __launch_bounds__(256) void gemm_mma(const float* __restrict__ bias_ext,
                                                float* __restrict__ dst_ext)
{
    extern __shared__ __nv_bfloat16 sm[];
    const int tid = threadIdx.x, wid = tid >> 5, lane = tid & 31;
    const int nt = blockIdx.x, mt = blockIdx.y;
    const int wm = wid >> 1, wn = wid & 1;

    const __nv_bfloat16* Ahi = MODE ? g_hsbhi : g_A1hi;
    const __nv_bfloat16* Alo = MODE ? g_hsblo : g_A1lo;
    const __nv_bfloat16* Bhi = MODE ? g_WoThi : g_WiThi;
    const __nv_bfloat16* Blo = MODE ? g_WoTlo : g_WiTlo;
    const float* bias = MODE ? bias_ext : g_bias1;

    const __nv_bfloat16* srcA[2] = { Ahi + (size_t)mt * 128 * H_SZ,
                                     Alo + (size_t)mt * 128 * H_SZ };
    const __nv_bfloat16* srcB[2] = { Bhi + (size_t)nt * 128 * H_SZ,
                                     Blo + (size_t)nt * 128 * H_SZ };

    const int r0 = tid >> 2, q0 = tid & 3;          // load mapping: idx = tid
    const int r1 = (tid + 256) >> 2, q1 = tid & 3;  // idx = tid + 256

    // ---- load chunk 0 into buffer 0 ----
#pragma unroll
    for (int t4 = 0; t4 < 4; t4++) {
        const __nv_bfloat16* s = (t4 < 2) ? srcA[t4] : srcB[t4 - 2];
        __nv_bfloat16* d = sm + t4 * TILE_BF;
        *(uint4*)(d + r0 * PAD + q0 * 8) = *(const uint4*)(s + (size_t)r0 * H_SZ + q0 * 8);
        *(uint4*)(d + r1 * PAD + q1 * 8) = *(const uint4*)(s + (size_t)r1 * H_SZ + q1 * 8);
    }
    __syncthreads();

    float acc[2][8][4];
#pragma unroll
    for (int mi = 0; mi < 2; mi++)
#pragma unroll
        for (int j = 0; j < 8; j++)
#pragma unroll
            for (int v = 0; v < 4; v++) acc[mi][j][v] = 0.f;

    const u32 sbase = smem_u32(sm);
    // ldmatrix lane addressing (bytes)
    const int a_row = lane & 15, a_kq = lane >> 4;                       // A tiles
    const int b_nr = (lane >> 4) * 8 + (lane & 7), b_kq = (lane >> 3) & 1; // B tiles

#pragma unroll 1
    for (int c = 0; c < 32; c++) {
        const int buf = c & 1;
        // prefetch next chunk into buf^1
        if (c < 31) {
            const int col0 = (c + 1) * 32;
#pragma unroll
            for (int t4 = 0; t4 < 4; t4++) {
                const __nv_bfloat16* s = ((t4 < 2) ? srcA[t4] : srcB[t4 - 2]) + col0;
                __nv_bfloat16* d = sm + ((buf ^ 1) * 4 + t4) * TILE_BF;
                *(uint4*)(d + r0 * PAD + q0 * 8) = *(const uint4*)(s + (size_t)r0 * H_SZ + q0 * 8);
                *(uint4*)(d + r1 * PAD + q1 * 8) = *(const uint4*)(s + (size_t)r1 * H_SZ + q1 * 8);
            }
        }

        const u32 bA = sbase + (u32)(buf * 4) * TILE_BF * 2;
#pragma unroll
        for (int s = 0; s < 2; s++) {            // two k16 steps per chunk
            const int kc0 = s * 16;
            u32 ahi[2][4], alo[2][4], bhi[8][2], blo[8][2];
#pragma unroll
            for (int mi = 0; mi < 2; mi++) {
                u32 off = (u32)((wm * 32 + mi * 16 + a_row) * PAD + kc0 + a_kq * 8) * 2;
                ldmx4(ahi[mi][0], ahi[mi][1], ahi[mi][2], ahi[mi][3], bA + 0 * TILE_BF * 2 + off);
                ldmx4(alo[mi][0], alo[mi][1], alo[mi][2], alo[mi][3], bA + 1 * TILE_BF * 2 + off);
            }
#pragma unroll
            for (int ni = 0; ni < 4; ni++) {
                u32 off = (u32)((wn * 64 + ni * 16 + b_nr) * PAD + kc0 + b_kq * 8) * 2;
                ldmx4(bhi[2*ni][0], bhi[2*ni][1], bhi[2*ni+1][0], bhi[2*ni+1][1],
                      bA + 2 * TILE_BF * 2 + off);
                ldmx4(blo[2*ni][0], blo[2*ni][1], blo[2*ni+1][0], blo[2*ni+1][1],
                      bA + 3 * TILE_BF * 2 + off);
            }
#pragma unroll
            for (int mi = 0; mi < 2; mi++)
#pragma unroll
                for (int j = 0; j < 8; j++) {
                    mma16816(acc[mi][j], ahi[mi], bhi[j]);
                    mma16816(acc[mi][j], ahi[mi], blo[j]);
                    mma16816(acc[mi][j], alo[mi], bhi[j]);
                }
        }
        __syncthreads();
    }

    // ---- epilogue ----
    const int gid = lane >> 2, qid = lane & 3;
#pragma unroll
    for (int mi = 0; mi < 2; mi++) {
#pragma unroll
        for (int j = 0; j < 8; j++) {
            int col = nt * 128 + wn * 64 + j * 8 + qid * 2;
            float2 bv = *(const float2*)(bias + col);
            int mA = mt * 128 + wm * 32 + mi * 16 + gid;
            int mB = mA + 8;
            float* dA; float* dB;
            if (MODE == 0) {
                dA = g_acc + (size_t)mA * H_SZ + col;
                dB = g_acc + (size_t)mB * H_SZ + col;
            } else {
                dA = dst_ext + ((size_t)(mA & 63) * T_STEPS + (mA >> 6)) * O_SZ + col;
                dB = dst_ext + ((size_t)(mB & 63) * T_STEPS + (mB >> 6)) * O_SZ + col;
            }
            *(float2*)dA = make_float2(acc[mi][j][0] + bv.x, acc[mi][j][1] + bv.y);
            *(float2*)dB = make_float2(acc[mi][j][2] + bv.x, acc[mi][j][3] + bv.y);
        }
    }
}

// ---------------------------------------------------------------------------
// Grid barrier (monotonic flag, replay-safe)
// ---------------------------------------------------------------------------
__device__ __forceinline__ void grid_barrier(int slot) {
    __syncthreads();
    if (threadIdx.x == 0) {
        volatile unsigned* fl = &g_flag[slot];
        unsigned prev = *fl;
        __threadfence();
        unsigned old = atomicAdd(&g_cnt[slot], 1u);
        if (old == NCTA - 1) {
            atomicExch(&g_cnt[slot], 0u);
            __threadfence();
            atomicAdd(&g_flag[slot], 1u);
        } else {
            while (*fl == prev) { }
        }
        __threadfence();
    }
    __syncthreads();
}

// ---------------------------------------------------------------------------
// Persistent recurrence: 128 CTAs = 4 col-tiles(256) x 32 k-chunks(32).
// 8x8 per-thread blocking, f32x2 FMA, fused reduce+tanh+bf16 split.
// ---------------------------------------------------------------------------
__global__ __launch_bounds__(256) void rec_persistent(
    const float* __restrict__ hidden0, const float* __restrict__ Wh,
    float* __restrict__ hid_out)
{
    __shared__ __align__(16) float Ws[32][256];
    __shared__ __align__(16) float As[32][64];

    const int tid = threadIdx.x;
    const int ct  = blockIdx.x & 3;
    const int kc  = blockIdx.x >> 2;

    {
        int r = tid >> 3, c0 = (tid & 7) * 32;
        const float* src = Wh + (size_t)(kc * 32 + r) * H_SZ + ct * 256 + c0;
#pragma unroll
        for (int i = 0; i < 8; i++)
            *(float4*)&Ws[r][c0 + i * 4] = *(const float4*)(src + i * 4);
    }

    const int wy = tid >> 5;
    const int tx = tid & 31;
    const int rr = tid >> 2, kq = tid & 3;

#pragma unroll 1
    for (int t = 0; t < T_STEPS; t++) {
        const float* src = t ? (g_hs + (size_t)(t - 1) * BH) : hidden0;
        const float* sp  = src + (size_t)rr * H_SZ + kc * 32 + kq * 8;
        float4 p0 = __ldcg((const float4*)(sp));
        float4 p1 = __ldcg((const float4*)(sp + 4));

        As[kq*8+0][rr] = p0.x; As[kq*8+1][rr] = p0.y;
        As[kq*8+2][rr] = p0.z; As[kq*8+3][rr] = p0.w;
        As[kq*8+4][rr] = p1.x; As[kq*8+5][rr] = p1.y;
        As[kq*8+6][rr] = p1.z; As[kq*8+7][rr] = p1.w;
        __syncthreads();

        u64 acc[8][4];
#pragma unroll
        for (int i = 0; i < 8; i++)
#pragma unroll
            for (int j = 0; j < 4; j++) acc[i][j] = 0ull;

#pragma unroll
        for (int kk = 0; kk < 32; kk++) {
            float4 a0 = *(const float4*)&As[kk][wy * 8];
            float4 a1 = *(const float4*)&As[kk][wy * 8 + 4];
            ulonglong2 w0 = *(const ulonglong2*)&Ws[kk][tx * 4];
            ulonglong2 w1 = *(const ulonglong2*)&Ws[kk][128 + tx * 4];
            u64 a2;
            a2 = pk2(a0.x); acc[0][0]=fma2(a2,w0.x,acc[0][0]); acc[0][1]=fma2(a2,w0.y,acc[0][1]); acc[0][2]=fma2(a2,w1.x,acc[0][2]); acc[0][3]=fma2(a2,w1.y,acc[0][3]);
            a2 = pk2(a0.y); acc[1][0]=fma2(a2,w0.x,acc[1][0]); acc[1][1]=fma2(a2,w0.y,acc[1][1]); acc[1][2]=fma2(a2,w1.x,acc[1][2]); acc[1][3]=fma2(a2,w1.y,acc[1][3]);
            a2 = pk2(a0.z); acc[2][0]=fma2(a2,w0.x,acc[2][0]); acc[2][1]=fma2(a2,w0.y,acc[2][1]); acc[2][2]=fma2(a2,w1.x,acc[2][2]); acc[2][3]=fma2(a2,w1.y,acc[2][3]);
            a2 = pk2(a0.w); acc[3][0]=fma2(a2,w0.x,acc[3][0]); acc[3][1]=fma2(a2,w0.y,acc[3][1]); acc[3][2]=fma2(a2,w1.x,acc[3][2]); acc[3][3]=fma2(a2,w1.y,acc[3][3]);
            a2 = pk2(a1.x); acc[4][0]=fma2(a2,w0.x,acc[4][0]); acc[4][1]=fma2(a2,w0.y,acc[4][1]); acc[4][2]=fma2(a2,w1.x,acc[4][2]); acc[4][3]=fma2(a2,w1.y,acc[4][3]);
            a2 = pk2(a1.y); acc[5][0]=fma2(a2,w0.x,acc[5][0]); acc[5][1]=fma2(a2,w0.y,acc[5][1]); acc[5][2]=fma2(a2,w1.x,acc[5][2]); acc[5][3]=fma2(a2,w1.y,acc[5][3]);
            a2 = pk2(a1.z); acc[6][0]=fma2(a2,w0.x,acc[6][0]); acc[6][1]=fma2(a2,w0.y,acc[6][1]); acc[6][2]=fma2(a2,w1.x,acc[6][2]); acc[6][3]=fma2(a2,w1.y,acc[6][3]);
            a2 = pk2(a1.w); acc[7][0]=fma2(a2,w0.x,acc[7][0]); acc[7][1]=fma2(a2,w0.y,acc[7][1]); acc[7][2]=fma2(a2,w1.x,acc[7][2]); acc[7][3]=fma2(a2,w1.y,acc[7][3]);
        }

        {
            float* p = g_parts + (size_t)kc * BH + (size_t)(wy * 8) * H_SZ
                     + ct * 256 + tx * 4;
#pragma unroll
            for (int i = 0; i < 8; i++) {
                float2 c0 = upk(acc[i][0]), c1 = upk(acc[i][1]);
                float2 c2 = upk(acc[i][2]), c3 = upk(acc[i][3]);
                *(float4*)(p + (size_t)i * H_SZ)       = make_float4(c0.x, c0.y, c1.x, c1.y);
                *(float4*)(p + (size_t)i * H_SZ + 128) = make_float4(c2.x, c2.y, c3.x, c3.y);
            }
        }

        grid_barrier(0);

        if (tid < 128) {
            size_t e = (size_t)blockIdx.x * 512 + (size_t)tid * 4;
            float4 a = *(const float4*)(g_acc + (size_t)t * BH + e);
#pragma unroll
            for (int k2 = 0; k2 < KC_REC; k2++) {
                float4 q = __ldcg((const float4*)(g_parts + (size_t)k2 * BH + e));
                a.x += q.x; a.y += q.y; a.z += q.z; a.w += q.w;
            }
            a.x = tanhf(a.x); a.y = tanhf(a.y); a.z = tanhf(a.z); a.w = tanhf(a.w);
            *(float4*)(g_hs + (size_t)t * BH + e) = a;

            __nv_bfloat16 h0 = __float2bfloat16(a.x), h1 = __float2bfloat16(a.y);
            __nv_bfloat16 h2 = __float2bfloat16(a.z), h3 = __float2bfloat16(a.w);
            __nv_bfloat16 hh[4] = {h0, h1, h2, h3};
            __nv_bfloat16 ll[4] = {
                __float2bfloat16(a.x - __bfloat162float(h0)),
                __float2bfloat16(a.y - __bfloat162float(h1)),
                __float2bfloat16(a.z - __bfloat162float(h2)),
                __float2bfloat16(a.w - __bfloat162float(h3))};
            *(uint2*)(g_hsbhi + (size_t)t * BH + e) = *(uint2*)hh;
            *(uint2*)(g_hsblo + (size_t)t * BH + e) = *(uint2*)ll;

            if (hid_out && t == T_STEPS - 1)
                *(float4*)(hid_out + e) = a;
        }

        grid_barrier(1);
    }
}

// ---------------------------------------------------------------------------
extern "C" void kernel_launch(void* const* d_in, const int* in_sizes, int n_in,
                              void* d_out, int out_size)
{
    const int*   input   = (const int*)  d_in[0];
    const float* hidden0 = (const float*)d_in[1];
    const float* emb     = (const float*)d_in[2];
    const float* Wi      = (const float*)d_in[3];
    const float* bi      = (const float*)d_in[4];
    const float* Wh      = (const float*)d_in[5];
    const float* bh      = (const float*)d_in[6];
    const float* Wo      = (const float*)d_in[7];
    const float* bo      = (const float*)d_in[8];
    float* out = (float*)d_out;

    float* hid_out = (out_size >= M_TOT * O_SZ + BH) ? out + (size_t)M_TOT * O_SZ
                                                     : (float*)0;

    static int smem_set = 0;
    if (!smem_set) {
        cudaFuncSetAttribute(gemm_mma<0>, cudaFuncAttributeMaxDynamicSharedMemorySize, SMEM_GEMM_BYTES);
        cudaFuncSetAttribute(gemm_mma<1>, cudaFuncAttributeMaxDynamicSharedMemorySize, SMEM_GEMM_BYTES);
        smem_set = 1;
    }

    prep_bias<<<4, 256>>>(bi, bh);
    prep_transpose<0><<<dim3(32, 32), 256>>>(Wi);
    prep_transpose<1><<<dim3(32, 32), 256>>>(Wo);
    prep_gather<<<8192, 256>>>(input, emb);

    gemm_mma<0><<<dim3(8, 128), 256, SMEM_GEMM_BYTES>>>((const float*)0, (float*)0);
    rec_persistent<<<NCTA, 256>>>(hidden0, Wh, hid_out);
    gemm_mma<1><<<dim3(8, 128), 256, SMEM_GEMM_BYTES>>>(bo, out);
}

// round 5
// speedup vs baseline: 1.5842x; 1.2229x over previous
#include <cuda_runtime.h>
#include <cuda_bf16.h>
#include <math.h>

#define T_STEPS 256
#define B_SZ    64
#define H_SZ    1024
#define O_SZ    1024
#define BH      (B_SZ * H_SZ)        // 65536
#define M_TOT   (T_STEPS * B_SZ)     // 16384
#define KSPLIT  8                    // recurrence k-split
#define NCTA    128
#define PAD     40                   // smem row stride (bf16) for big gemm tiles
#define RPAD    136                  // smem row stride (bf16) for rec tiles (128+8)

typedef unsigned long long u64;
typedef unsigned int u32;

__device__ __forceinline__ u32 smem_u32(const void* p) {
    u32 a; asm("{ .reg .u64 t; cvta.to.shared.u64 t, %1; cvt.u32.u64 %0, t; }"
               : "=r"(a) : "l"(p));
    return a;
}

// ---- mma.sync helpers (plain PTX, validated on this build) -----------------
__device__ __forceinline__ void ldmx4(u32& r0, u32& r1, u32& r2, u32& r3, u32 a) {
    asm volatile("ldmatrix.sync.aligned.m8n8.x4.shared.b16 {%0,%1,%2,%3}, [%4];"
                 : "=r"(r0), "=r"(r1), "=r"(r2), "=r"(r3) : "r"(a));
}
__device__ __forceinline__ void mma16816(float* c, const u32* a, const u32* b) {
    asm volatile(
        "mma.sync.aligned.m16n8k16.row.col.f32.bf16.bf16.f32 "
        "{%0,%1,%2,%3}, {%4,%5,%6,%7}, {%8,%9}, {%0,%1,%2,%3};"
        : "+f"(c[0]), "+f"(c[1]), "+f"(c[2]), "+f"(c[3])
        : "r"(a[0]), "r"(a[1]), "r"(a[2]), "r"(a[3]), "r"(b[0]), "r"(b[1]));
}

// ---- scratch ---------------------------------------------------------------
__device__ float g_acc[(size_t)M_TOT * H_SZ];      // ix + bi + bh
__device__ __nv_bfloat16 g_A1hi[(size_t)M_TOT * H_SZ];
__device__ __nv_bfloat16 g_A1lo[(size_t)M_TOT * H_SZ];
__device__ __nv_bfloat16 g_hsbhi[(size_t)M_TOT * H_SZ];   // h states hi (bf16)
__device__ __nv_bfloat16 g_hsblo[(size_t)M_TOT * H_SZ];   // h states lo
__device__ __nv_bfloat16 g_h0hi[BH];
__device__ __nv_bfloat16 g_h0lo[BH];
__device__ __nv_bfloat16 g_WiThi[(size_t)H_SZ * H_SZ];    // [n][k]
__device__ __nv_bfloat16 g_WiTlo[(size_t)H_SZ * H_SZ];
__device__ __nv_bfloat16 g_WoThi[(size_t)H_SZ * O_SZ];
__device__ __nv_bfloat16 g_WoTlo[(size_t)H_SZ * O_SZ];
__device__ __nv_bfloat16 g_WhThi[(size_t)H_SZ * H_SZ];
__device__ __nv_bfloat16 g_WhTlo[(size_t)H_SZ * H_SZ];
__device__ float g_parts[(size_t)KSPLIT * BH];
__device__ float g_bias1[H_SZ];
__device__ unsigned g_cnt[2];
__device__ unsigned g_flag[2];

// ---------------------------------------------------------------------------
// Prep kernels
// ---------------------------------------------------------------------------
__global__ void prep_bias(const float* __restrict__ bi, const float* __restrict__ bh) {
    int i = blockIdx.x * 256 + threadIdx.x;
    g_bias1[i] = bi[i] + bh[i];
}

template<int W>
__global__ void prep_transpose(const float* __restrict__ src) {
    __shared__ float ts[32][33];
    __nv_bfloat16* dhi = (W == 0) ? g_WiThi : (W == 1) ? g_WoThi : g_WhThi;
    __nv_bfloat16* dlo = (W == 0) ? g_WiTlo : (W == 1) ? g_WoTlo : g_WhTlo;
    int n0 = blockIdx.x * 32, k0 = blockIdx.y * 32;
    int tx = threadIdx.x & 31, ty = threadIdx.x >> 5;
#pragma unroll
    for (int i = 0; i < 4; i++)
        ts[ty + i * 8][tx] = src[(size_t)(k0 + ty + i * 8) * H_SZ + n0 + tx];
    __syncthreads();
#pragma unroll
    for (int i = 0; i < 4; i++) {
        int n = n0 + ty + i * 8;
        float v = ts[tx][ty + i * 8];
        __nv_bfloat16 h = __float2bfloat16(v);
        float r = v - __bfloat162float(h);
        dhi[(size_t)n * H_SZ + k0 + tx] = h;
        dlo[(size_t)n * H_SZ + k0 + tx] = __float2bfloat16(r);
    }
}

struct __align__(16) bf8 { __nv_bfloat16 v[8]; };

__global__ void prep_gather(const int* __restrict__ input, const float* __restrict__ emb) {
    size_t g = (size_t)blockIdx.x * 256 + threadIdx.x;
    size_t e = g * 8;
    int m = (int)(e >> 10), k = (int)(e & 1023);
    int t = m >> 6, b = m & 63;
    int row = input[b * T_STEPS + t];
    float4 v0 = *(const float4*)(emb + (size_t)row * H_SZ + k);
    float4 v1 = *(const float4*)(emb + (size_t)row * H_SZ + k + 4);
    float vv[8] = {v0.x, v0.y, v0.z, v0.w, v1.x, v1.y, v1.z, v1.w};
    bf8 hh, ll;
#pragma unroll
    for (int i = 0; i < 8; i++) {
        __nv_bfloat16 h = __float2bfloat16(vv[i]);
        hh.v[i] = h;
        ll.v[i] = __float2bfloat16(vv[i] - __bfloat162float(h));
    }
    *(bf8*)(g_A1hi + e) = hh;
    *(bf8*)(g_A1lo + e) = ll;
}

__global__ void prep_h0(const float* __restrict__ hidden0) {
    size_t e = ((size_t)blockIdx.x * 256 + threadIdx.x) * 4;
    float4 v = *(const float4*)(hidden0 + e);
    float vv[4] = {v.x, v.y, v.z, v.w};
    __nv_bfloat16 hh[4], ll[4];
#pragma unroll
    for (int i = 0; i < 4; i++) {
        hh[i] = __float2bfloat16(vv[i]);
        ll[i] = __float2bfloat16(vv[i] - __bfloat162float(hh[i]));
    }
    *(uint2*)(g_h0hi + e) = *(uint2*)hh;
    *(uint2*)(g_h0lo + e) = *(uint2*)ll;
}

// ---------------------------------------------------------------------------
// mma.sync big GEMM (unchanged from R4, passing): 128x128 CTA tile.
// ---------------------------------------------------------------------------
#define TILE_BF (128 * PAD)
#define SMEM_GEMM_BYTES (2 * 4 * TILE_BF * 2)

template<int MODE>
__global__ __launch_bounds__(256) void gemm_mma(const float* __restrict__ bias_ext,
                                                float* __restrict__ dst_ext)
{
    extern __shared__ __nv_bfloat16 sm[];
    const int tid = threadIdx.x, wid = tid >> 5, lane = tid & 31;
    const int nt = blockIdx.x, mt = blockIdx.y;
    const int wm = wid >> 1, wn = wid & 1;

    const __nv_bfloat16* Ahi = MODE ? g_hsbhi : g_A1hi;
    const __nv_bfloat16* Alo = MODE ? g_hsblo : g_A1lo;
    const __nv_bfloat16* Bhi = MODE ? g_WoThi : g_WiThi;
    const __nv_bfloat16* Blo = MODE ? g_WoTlo : g_WiTlo;
    const float* bias = MODE ? bias_ext : g_bias1;

    const __nv_bfloat16* srcA[2] = { Ahi + (size_t)mt * 128 * H_SZ,
                                     Alo + (size_t)mt * 128 * H_SZ };
    const __nv_bfloat16* srcB[2] = { Bhi + (size_t)nt * 128 * H_SZ,
                                     Blo + (size_t)nt * 128 * H_SZ };

    const int r0 = tid >> 2, q0 = tid & 3;
    const int r1 = (tid + 256) >> 2, q1 = tid & 3;

#pragma unroll
    for (int t4 = 0; t4 < 4; t4++) {
        const __nv_bfloat16* s = (t4 < 2) ? srcA[t4] : srcB[t4 - 2];
        __nv_bfloat16* d = sm + t4 * TILE_BF;
        *(uint4*)(d + r0 * PAD + q0 * 8) = *(const uint4*)(s + (size_t)r0 * H_SZ + q0 * 8);
        *(uint4*)(d + r1 * PAD + q1 * 8) = *(const uint4*)(s + (size_t)r1 * H_SZ + q1 * 8);
    }
    __syncthreads();

    float acc[2][8][4];
#pragma unroll
    for (int mi = 0; mi < 2; mi++)
#pragma unroll
        for (int j = 0; j < 8; j++)
#pragma unroll
            for (int v = 0; v < 4; v++) acc[mi][j][v] = 0.f;

    const u32 sbase = smem_u32(sm);
    const int a_row = lane & 15, a_kq = lane >> 4;
    const int b_nr = (lane >> 4) * 8 + (lane & 7), b_kq = (lane >> 3) & 1;

#pragma unroll 1
    for (int c = 0; c < 32; c++) {
        const int buf = c & 1;
        if (c < 31) {
            const int col0 = (c + 1) * 32;
#pragma unroll
            for (int t4 = 0; t4 < 4; t4++) {
                const __nv_bfloat16* s = ((t4 < 2) ? srcA[t4] : srcB[t4 - 2]) + col0;
                __nv_bfloat16* d = sm + ((buf ^ 1) * 4 + t4) * TILE_BF;
                *(uint4*)(d + r0 * PAD + q0 * 8) = *(const uint4*)(s + (size_t)r0 * H_SZ + q0 * 8);
                *(uint4*)(d + r1 * PAD + q1 * 8) = *(const uint4*)(s + (size_t)r1 * H_SZ + q1 * 8);
            }
        }

        const u32 bA = sbase + (u32)(buf * 4) * TILE_BF * 2;
#pragma unroll
        for (int s = 0; s < 2; s++) {
            const int kc0 = s * 16;
            u32 ahi[2][4], alo[2][4], bhi[8][2], blo[8][2];
#pragma unroll
            for (int mi = 0; mi < 2; mi++) {
                u32 off = (u32)((wm * 32 + mi * 16 + a_row) * PAD + kc0 + a_kq * 8) * 2;
                ldmx4(ahi[mi][0], ahi[mi][1], ahi[mi][2], ahi[mi][3], bA + 0 * TILE_BF * 2 + off);
                ldmx4(alo[mi][0], alo[mi][1], alo[mi][2], alo[mi][3], bA + 1 * TILE_BF * 2 + off);
            }
#pragma unroll
            for (int ni = 0; ni < 4; ni++) {
                u32 off = (u32)((wn * 64 + ni * 16 + b_nr) * PAD + kc0 + b_kq * 8) * 2;
                ldmx4(bhi[2*ni][0], bhi[2*ni][1], bhi[2*ni+1][0], bhi[2*ni+1][1],
                      bA + 2 * TILE_BF * 2 + off);
                ldmx4(blo[2*ni][0], blo[2*ni][1], blo[2*ni+1][0], blo[2*ni+1][1],
                      bA + 3 * TILE_BF * 2 + off);
            }
#pragma unroll
            for (int mi = 0; mi < 2; mi++)
#pragma unroll
                for (int j = 0; j < 8; j++) {
                    mma16816(acc[mi][j], ahi[mi], bhi[j]);
                    mma16816(acc[mi][j], ahi[mi], blo[j]);
                    mma16816(acc[mi][j], alo[mi], bhi[j]);
                }
        }
        __syncthreads();
    }

    const int gid = lane >> 2, qid = lane & 3;
#pragma unroll
    for (int mi = 0; mi < 2; mi++) {
#pragma unroll
        for (int j = 0; j < 8; j++) {
            int col = nt * 128 + wn * 64 + j * 8 + qid * 2;
            float2 bv = *(const float2*)(bias + col);
            int mA = mt * 128 + wm * 32 + mi * 16 + gid;
            int mB = mA + 8;
            float* dA; float* dB;
            if (MODE == 0) {
                dA = g_acc + (size_t)mA * H_SZ + col;
                dB = g_acc + (size_t)mB * H_SZ + col;
            } else {
                dA = dst_ext + ((size_t)(mA & 63) * T_STEPS + (mA >> 6)) * O_SZ + col;
                dB = dst_ext + ((size_t)(mB & 63) * T_STEPS + (mB >> 6)) * O_SZ + col;
            }
            *(float2*)dA = make_float2(acc[mi][j][0] + bv.x, acc[mi][j][1] + bv.y);
            *(float2*)dB = make_float2(acc[mi][j][2] + bv.x, acc[mi][j][3] + bv.y);
        }
    }
}

// ---------------------------------------------------------------------------
// Grid barrier (monotonic flag, replay-safe)
// ---------------------------------------------------------------------------
__device__ __forceinline__ void grid_barrier(int slot) {
    __syncthreads();
    if (threadIdx.x == 0) {
        volatile unsigned* fl = &g_flag[slot];
        unsigned prev = *fl;
        __threadfence();
        unsigned old = atomicAdd(&g_cnt[slot], 1u);
        if (old == NCTA - 1) {
            atomicExch(&g_cnt[slot], 0u);
            __threadfence();
            atomicAdd(&g_flag[slot], 1u);
        } else {
            while (*fl == prev) { }
        }
        __threadfence();
    }
    __syncthreads();
}

// ---------------------------------------------------------------------------
// Persistent recurrence with mma.sync.
// 128 CTAs: ct = blk & 15 (n-tile of 64), kc = blk >> 4 (k-chunk of 128).
// Wh tile (bf16 hi/lo, [n][k]) resident in smem for all 256 steps.
// Per step: load h(t-1) hi/lo slice into smem, 3-term mma (M64 N64 K128),
// fp32 partial -> gmem, barrier, fused reduce+tanh+split, barrier.
// ---------------------------------------------------------------------------
#define R_WHI 0
#define R_WLO (64 * RPAD)
#define R_AHI (2 * 64 * RPAD)
#define R_ALO (3 * 64 * RPAD)
#define SMEM_REC_BYTES (4 * 64 * RPAD * 2)

__global__ __launch_bounds__(256) void rec_mma(float* __restrict__ hid_out)
{
    extern __shared__ __nv_bfloat16 rs[];
    const int tid = threadIdx.x, wid = tid >> 5, lane = tid & 31;
    const int ct  = blockIdx.x & 15;
    const int kc  = blockIdx.x >> 4;
    const int wm  = wid >> 1, wn = wid & 1;

    // one-time Wh tile load: rows n = ct*64 .. +64, cols k = kc*128 .. +128
    {
        const size_t base = (size_t)(ct * 64) * H_SZ + kc * 128;
#pragma unroll
        for (int i = 0; i < 4; i++) {
            int ch = tid + i * 256;          // 0..1023
            int r  = ch >> 4;                // 0..63
            int co = (ch & 15) * 8;          // 0..120
            *(uint4*)(rs + R_WHI + r * RPAD + co) =
                *(const uint4*)(g_WhThi + base + (size_t)r * H_SZ + co);
            *(uint4*)(rs + R_WLO + r * RPAD + co) =
                *(const uint4*)(g_WhTlo + base + (size_t)r * H_SZ + co);
        }
    }

    const u32 sbase = smem_u32(rs);
    const int a_row = lane & 15, a_kq = lane >> 4;
    const int b_nr = (lane >> 4) * 8 + (lane & 7), b_kq = (lane >> 3) & 1;
    const int gid = lane >> 2, qid = lane & 3;

#pragma unroll 1
    for (int t = 0; t < T_STEPS; t++) {
        const __nv_bfloat16* hhi = t ? (g_hsbhi + (size_t)(t - 1) * BH) : g_h0hi;
        const __nv_bfloat16* hlo = t ? (g_hsblo + (size_t)(t - 1) * BH) : g_h0lo;

        // load h slice: rows b = 0..63, cols k = kc*128 .. +128
#pragma unroll
        for (int i = 0; i < 4; i++) {
            int ch = tid + i * 256;
            int r  = ch >> 4;
            int co = (ch & 15) * 8;
            size_t off = (size_t)r * H_SZ + kc * 128 + co;
            *(uint4*)(rs + R_AHI + r * RPAD + co) = __ldcg((const uint4*)(hhi + off));
            *(uint4*)(rs + R_ALO + r * RPAD + co) = __ldcg((const uint4*)(hlo + off));
        }
        __syncthreads();

        float acc[4][4];
#pragma unroll
        for (int j = 0; j < 4; j++)
#pragma unroll
            for (int v = 0; v < 4; v++) acc[j][v] = 0.f;

#pragma unroll
        for (int ks = 0; ks < 8; ks++) {
            const int k0 = ks * 16;
            u32 ahi[4], alo[4], bhi[4][2], blo[4][2];
            {
                u32 off = (u32)((wm * 16 + a_row) * RPAD + k0 + a_kq * 8) * 2;
                ldmx4(ahi[0], ahi[1], ahi[2], ahi[3], sbase + R_AHI * 2 + off);
                ldmx4(alo[0], alo[1], alo[2], alo[3], sbase + R_ALO * 2 + off);
            }
#pragma unroll
            for (int ni = 0; ni < 2; ni++) {
                u32 off = (u32)((wn * 32 + ni * 16 + b_nr) * RPAD + k0 + b_kq * 8) * 2;
                ldmx4(bhi[2*ni][0], bhi[2*ni][1], bhi[2*ni+1][0], bhi[2*ni+1][1],
                      sbase + R_WHI * 2 + off);
                ldmx4(blo[2*ni][0], blo[2*ni][1], blo[2*ni+1][0], blo[2*ni+1][1],
                      sbase + R_WLO * 2 + off);
            }
#pragma unroll
            for (int j = 0; j < 4; j++) {
                mma16816(acc[j], ahi, bhi[j]);
                mma16816(acc[j], ahi, blo[j]);
                mma16816(acc[j], alo, bhi[j]);
            }
        }

        // partial store: rows wm*16+gid(+8), cols ct*64 + wn*32 + j*8 + qid*2
        {
            float* p0 = g_parts + (size_t)kc * BH
                      + (size_t)(wm * 16 + gid) * H_SZ + ct * 64 + wn * 32;
            float* p1 = p0 + 8 * H_SZ;
#pragma unroll
            for (int j = 0; j < 4; j++) {
                *(float2*)(p0 + j * 8 + qid * 2) = make_float2(acc[j][0], acc[j][1]);
                *(float2*)(p1 + j * 8 + qid * 2) = make_float2(acc[j][2], acc[j][3]);
            }
        }

        grid_barrier(0);

        // fused reduce + tanh + bf16 hi/lo split
        if (tid < 128) {
            size_t e = (size_t)blockIdx.x * 512 + (size_t)tid * 4;
            float4 a = *(const float4*)(g_acc + (size_t)t * BH + e);
#pragma unroll
            for (int k2 = 0; k2 < KSPLIT; k2++) {
                float4 q = __ldcg((const float4*)(g_parts + (size_t)k2 * BH + e));
                a.x += q.x; a.y += q.y; a.z += q.z; a.w += q.w;
            }
            a.x = tanhf(a.x); a.y = tanhf(a.y); a.z = tanhf(a.z); a.w = tanhf(a.w);

            __nv_bfloat16 h0 = __float2bfloat16(a.x), h1 = __float2bfloat16(a.y);
            __nv_bfloat16 h2 = __float2bfloat16(a.z), h3 = __float2bfloat16(a.w);
            __nv_bfloat16 hh[4] = {h0, h1, h2, h3};
            __nv_bfloat16 ll[4] = {
                __float2bfloat16(a.x - __bfloat162float(h0)),
                __float2bfloat16(a.y - __bfloat162float(h1)),
                __float2bfloat16(a.z - __bfloat162float(h2)),
                __float2bfloat16(a.w - __bfloat162float(h3))};
            *(uint2*)(g_hsbhi + (size_t)t * BH + e) = *(uint2*)hh;
            *(uint2*)(g_hsblo + (size_t)t * BH + e) = *(uint2*)ll;

            if (hid_out && t == T_STEPS - 1)
                *(float4*)(hid_out + e) = a;
        }

        grid_barrier(1);
    }
}

// ---------------------------------------------------------------------------
extern "C" void kernel_launch(void* const* d_in, const int* in_sizes, int n_in,
                              void* d_out, int out_size)
{
    const int*   input   = (const int*)  d_in[0];
    const float* hidden0 = (const float*)d_in[1];
    const float* emb     = (const float*)d_in[2];
    const float* Wi      = (const float*)d_in[3];
    const float* bi      = (const float*)d_in[4];
    const float* Wh      = (const float*)d_in[5];
    const float* bh      = (const float*)d_in[6];
    const float* Wo      = (const float*)d_in[7];
    const float* bo      = (const float*)d_in[8];
    float* out = (float*)d_out;

    float* hid_out = (out_size >= M_TOT * O_SZ + BH) ? out + (size_t)M_TOT * O_SZ
                                                     : (float*)0;

    cudaFuncSetAttribute(gemm_mma<0>, cudaFuncAttributeMaxDynamicSharedMemorySize, SMEM_GEMM_BYTES);
    cudaFuncSetAttribute(gemm_mma<1>, cudaFuncAttributeMaxDynamicSharedMemorySize, SMEM_GEMM_BYTES);
    cudaFuncSetAttribute(rec_mma, cudaFuncAttributeMaxDynamicSharedMemorySize, SMEM_REC_BYTES);

    prep_bias<<<4, 256>>>(bi, bh);
    prep_transpose<0><<<dim3(32, 32), 256>>>(Wi);
    prep_transpose<1><<<dim3(32, 32), 256>>>(Wo);
    prep_transpose<2><<<dim3(32, 32), 256>>>(Wh);
    prep_h0<<<64, 256>>>(hidden0);
    prep_gather<<<8192, 256>>>(input, emb);

    gemm_mma<0><<<dim3(8, 128), 256, SMEM_GEMM_BYTES>>>((const float*)0, (float*)0);
    rec_mma<<<NCTA, 256, SMEM_REC_BYTES>>>(hid_out);
    gemm_mma<1><<<dim3(8, 128), 256, SMEM_GEMM_BYTES>>>(bo, out);
}